// round 1
// baseline (speedup 1.0000x reference)
#include <cuda_runtime.h>
#include <cstdint>
#include <math.h>

// ---------------- problem constants ----------------
#define HW      16384           // 128*128 spatial
#define GW      128
#define CH      256
#define KTOT    2304            // 256*9
#define NANCH   147456          // HW*9
#define NSORT   262144          // 2^18 padded
#define TOPK    6000
#define POSTK   300
#define STRIDE  8.0f
#define IMSZ    1024.0f
#define DWCLIP  4.135166556742356f
#define NMSTHR  0.7f
#define MINSZ   16.0f

// ---------------- scratch (device globals; no allocations allowed) ----------------
__device__ float g_rpnfeat[CH * HW];                 // 16.8 MB
__device__ float g_boxes[NANCH * 4];                 // 2.36 MB (unclipped decoded)
__device__ unsigned long long g_keys[NSORT];         // 2 MB sort keys

// =====================================================================
// Kernel 1: 3x3 conv 256->256 + bias + ReLU.  Implicit-GEMM:
//   C[oc, p] = sum_k W[oc,k] * B[k,p],  k = ic*9 + ky*3 + kx
// Tile: BM=128 oc, BN=64 pixels, BK=16, 256 threads, TM=8 x TN=4.
// =====================================================================
__global__ __launch_bounds__(256)
void conv3x3_relu(const float* __restrict__ feat, const float* __restrict__ w,
                  const float* __restrict__ bias)
{
    __shared__ float As[16][128];
    __shared__ float Bs[16][64];

    const int tid = threadIdx.x;
    const int tx = tid & 15;        // N dim (pixels)
    const int ty = tid >> 4;        // M dim (oc)
    const int p0  = blockIdx.x * 64;
    const int oc0 = blockIdx.y * 128;
    const int y   = p0 >> 7;        // row of this pixel tile
    const int x0  = p0 & 127;       // 0 or 64

    float acc[8][4];
#pragma unroll
    for (int m = 0; m < 8; m++)
#pragma unroll
        for (int n = 0; n < 4; n++) acc[m][n] = 0.f;

    for (int kb = 0; kb < KTOT; kb += 16) {
        // load A tile: 16 x 128 = 2048 elems, 8 per thread
#pragma unroll
        for (int i = 0; i < 8; i++) {
            int idx = tid + i * 256;
            int oc = idx >> 4, kk = idx & 15;
            As[kk][oc] = w[(oc0 + oc) * KTOT + kb + kk];
        }
        // load B tile: 16 x 64 = 1024 elems, 4 per thread (implicit im2col)
#pragma unroll
        for (int i = 0; i < 4; i++) {
            int idx = tid + i * 256;
            int kk = idx >> 6, px = idx & 63;
            int k  = kb + kk;
            int ic = k / 9;
            int r  = k - ic * 9;
            int ky = r / 3;
            int kx = r - ky * 3;
            int yy = y + ky - 1;
            int xx = x0 + px + kx - 1;
            float v = 0.f;
            if ((unsigned)yy < 128u && (unsigned)xx < 128u)
                v = feat[ic * HW + (yy << 7) + xx];
            Bs[kk][px] = v;
        }
        __syncthreads();
#pragma unroll
        for (int kk = 0; kk < 16; ++kk) {
            float4 b4 = *reinterpret_cast<const float4*>(&Bs[kk][tx * 4]);
            float4 a0 = *reinterpret_cast<const float4*>(&As[kk][ty * 8]);
            float4 a1 = *reinterpret_cast<const float4*>(&As[kk][ty * 8 + 4]);
            float av[8] = {a0.x, a0.y, a0.z, a0.w, a1.x, a1.y, a1.z, a1.w};
            float bv[4] = {b4.x, b4.y, b4.z, b4.w};
#pragma unroll
            for (int m = 0; m < 8; m++)
#pragma unroll
                for (int n = 0; n < 4; n++)
                    acc[m][n] = fmaf(av[m], bv[n], acc[m][n]);
        }
        __syncthreads();
    }
#pragma unroll
    for (int m = 0; m < 8; m++) {
        int oc = oc0 + ty * 8 + m;
        float bb = bias[oc];
        float4 r;
        r.x = fmaxf(acc[m][0] + bb, 0.f);
        r.y = fmaxf(acc[m][1] + bb, 0.f);
        r.z = fmaxf(acc[m][2] + bb, 0.f);
        r.w = fmaxf(acc[m][3] + bb, 0.f);
        *reinterpret_cast<float4*>(&g_rpnfeat[oc * HW + p0 + tx * 4]) = r;
    }
}

// =====================================================================
// Kernel 2: 1x1 heads (9 cls + 36 bbox) + anchor decode + sigmoid + keys.
// One thread per pixel; 45 accumulators over 256 channels.
// =====================================================================
__global__ __launch_bounds__(128)
void heads_decode(const float* __restrict__ cls_w, const float* __restrict__ cls_b,
                  const float* __restrict__ bbox_w, const float* __restrict__ bbox_b)
{
    __shared__ float ws[45][256];           // 46080 B static smem
    const int tid = threadIdx.x;
    for (int i = tid; i < 9 * 256; i += 128)  ws[i >> 8][i & 255] = cls_w[i];
    for (int i = tid; i < 36 * 256; i += 128) ws[9 + (i >> 8)][i & 255] = bbox_w[i];
    __syncthreads();

    const int y = blockIdx.x;
    const int x = tid;
    const int p = (y << 7) + x;

    float acc[45];
#pragma unroll
    for (int j = 0; j < 45; j++) acc[j] = 0.f;

    const float* rf = g_rpnfeat;
    for (int c = 0; c < 256; c++) {
        float v = rf[c * HW + p];
#pragma unroll
        for (int j = 0; j < 45; j++) acc[j] = fmaf(ws[j][c], v, acc[j]);
    }

    const float AR[3]  = {0.5f, 1.0f, 2.0f};
    const float SCL[3] = {128.f, 256.f, 512.f};
    const float sx = (float)x * STRIDE;
    const float sy = (float)y * STRIDE;

#pragma unroll
    for (int a = 0; a < 9; a++) {
        int ia = a / 3, is_ = a - ia * 3;
        float hr  = sqrtf(AR[ia]);
        float wr  = __fdiv_rn(1.0f, hr);
        float hsv = __fmul_rn(hr, SCL[is_]);
        float wsv = __fmul_rn(wr, SCL[is_]);
        float bx1 = rintf(__fmul_rn(-wsv, 0.5f));
        float by1 = rintf(__fmul_rn(-hsv, 0.5f));
        float bx2 = rintf(__fmul_rn(wsv, 0.5f));
        float by2 = rintf(__fmul_rn(hsv, 0.5f));
        float ax1 = __fadd_rn(sx, bx1), ay1 = __fadd_rn(sy, by1);
        float ax2 = __fadd_rn(sx, bx2), ay2 = __fadd_rn(sy, by2);
        float aw = __fsub_rn(ax2, ax1), ah = __fsub_rn(ay2, ay1);
        float cx = __fadd_rn(ax1, __fmul_rn(0.5f, aw));
        float cy = __fadd_rn(ay1, __fmul_rn(0.5f, ah));

        float dx = acc[9 + a * 4 + 0] + bbox_b[a * 4 + 0];
        float dy = acc[9 + a * 4 + 1] + bbox_b[a * 4 + 1];
        float dw = fminf(acc[9 + a * 4 + 2] + bbox_b[a * 4 + 2], DWCLIP);
        float dh = fminf(acc[9 + a * 4 + 3] + bbox_b[a * 4 + 3], DWCLIP);

        float px = __fadd_rn(__fmul_rn(dx, aw), cx);
        float py = __fadd_rn(__fmul_rn(dy, ah), cy);
        float pw = __fmul_rn((float)exp((double)dw), aw);   // exact expf via double
        float ph = __fmul_rn((float)exp((double)dh), ah);

        float x1 = __fsub_rn(px, __fmul_rn(0.5f, pw));
        float y1 = __fsub_rn(py, __fmul_rn(0.5f, ph));
        float x2 = __fadd_rn(px, __fmul_rn(0.5f, pw));
        float y2 = __fadd_rn(py, __fmul_rn(0.5f, ph));

        int idx = p * 9 + a;
        g_boxes[idx * 4 + 0] = x1;
        g_boxes[idx * 4 + 1] = y1;
        g_boxes[idx * 4 + 2] = x2;
        g_boxes[idx * 4 + 3] = y2;

        float cls = acc[a] + cls_b[a];
        float s = (float)(1.0 / (1.0 + exp(-(double)cls)));  // monotone, ~correctly rounded
        unsigned sb = __float_as_uint(s);                    // s>0 -> bits monotone
        g_keys[idx] = ((unsigned long long)sb << 32) | (unsigned)(0xFFFFFFFFu - (unsigned)idx);
    }
}

__global__ void pad_keys()
{
    int i = NANCH + blockIdx.x * blockDim.x + threadIdx.x;
    if (i < NSORT) g_keys[i] = 0ull;
}

// =====================================================================
// Bitonic sort of g_keys, descending (unique keys -> stable wrt index).
// =====================================================================
__global__ __launch_bounds__(1024)
void bitonic_local()
{
    __shared__ unsigned long long s[2048];
    const int base = blockIdx.x << 11;
    s[threadIdx.x]        = g_keys[base + threadIdx.x];
    s[threadIdx.x + 1024] = g_keys[base + threadIdx.x + 1024];
    __syncthreads();
    for (int k = 2; k <= 2048; k <<= 1) {
        for (int j = k >> 1; j > 0; j >>= 1) {
            int t = threadIdx.x;
            int i = (t << 1) - (t & (j - 1));
            bool desc = (((base + i) & k) == 0);
            unsigned long long a = s[i], b = s[i + j];
            if ((a < b) == desc) { s[i] = b; s[i + j] = a; }
            __syncthreads();
        }
    }
    g_keys[base + threadIdx.x]        = s[threadIdx.x];
    g_keys[base + threadIdx.x + 1024] = s[threadIdx.x + 1024];
}

__global__ __launch_bounds__(256)
void bitonic_global(int k, int j)
{
    int t = blockIdx.x * blockDim.x + threadIdx.x;   // NSORT/2 threads
    int i = (t << 1) - (t & (j - 1));
    bool desc = ((i & k) == 0);
    unsigned long long a = g_keys[i], b = g_keys[i + j];
    if ((a < b) == desc) { g_keys[i] = b; g_keys[i + j] = a; }
}

__global__ __launch_bounds__(1024)
void bitonic_finish(int k)
{
    __shared__ unsigned long long s[2048];
    const int base = blockIdx.x << 11;
    s[threadIdx.x]        = g_keys[base + threadIdx.x];
    s[threadIdx.x + 1024] = g_keys[base + threadIdx.x + 1024];
    __syncthreads();
    for (int j = 1024; j > 0; j >>= 1) {
        int t = threadIdx.x;
        int i = (t << 1) - (t & (j - 1));
        bool desc = (((base + i) & k) == 0);
        unsigned long long a = s[i], b = s[i + j];
        if ((a < b) == desc) { s[i] = b; s[i + j] = a; }
        __syncthreads();
    }
    g_keys[base + threadIdx.x]        = s[threadIdx.x];
    g_keys[base + threadIdx.x + 1024] = s[threadIdx.x + 1024];
}

// =====================================================================
// Kernel: clip + min-size validity + greedy NMS (early exit at 300 kept)
// + write final 300x5 output. Single block, boxes in smem.
// smem: x1,y1,x2,y2,area float[6000], removed u8[6000] = 126000 B dynamic
// =====================================================================
__global__ __launch_bounds__(1024)
void nms_out(float* __restrict__ out)
{
    extern __shared__ float sm[];
    float* sx1 = sm;
    float* sy1 = sm + TOPK;
    float* sx2 = sm + 2 * TOPK;
    float* sy2 = sm + 3 * TOPK;
    float* sar = sm + 4 * TOPK;
    unsigned char* srem = (unsigned char*)(sm + 5 * TOPK);
    __shared__ int keepList[POSTK];

    const int tid = threadIdx.x;
    for (int i = tid; i < TOPK; i += blockDim.x) {
        unsigned long long key = g_keys[i];
        unsigned idx = 0xFFFFFFFFu - (unsigned)(key & 0xFFFFFFFFull);
        float b0 = g_boxes[idx * 4 + 0];
        float b1 = g_boxes[idx * 4 + 1];
        float b2 = g_boxes[idx * 4 + 2];
        float b3 = g_boxes[idx * 4 + 3];
        float x1 = fminf(fmaxf(b0, 0.f), IMSZ);
        float y1 = fminf(fmaxf(b1, 0.f), IMSZ);
        float x2 = fminf(fmaxf(b2, 0.f), IMSZ);
        float y2 = fminf(fmaxf(b3, 0.f), IMSZ);
        float wv = __fsub_rn(x2, x1);
        float hv = __fsub_rn(y2, y1);
        sx1[i] = x1; sy1[i] = y1; sx2[i] = x2; sy2[i] = y2;
        sar[i] = __fmul_rn(wv, hv);
        srem[i] = (wv >= MINSZ && hv >= MINSZ) ? 0 : 1;
    }
    __syncthreads();

    int count = 0;
    for (int i = 0; i < TOPK; i++) {
        if (srem[i] == 0) {
            if (tid == 0) keepList[count] = i;
            count++;
            float bx1 = sx1[i], by1 = sy1[i], bx2 = sx2[i], by2 = sy2[i], ba = sar[i];
            for (int j = i + 1 + tid; j < TOPK; j += blockDim.x) {
                if (srem[j]) continue;
                float xx1 = fmaxf(bx1, sx1[j]);
                float yy1 = fmaxf(by1, sy1[j]);
                float xx2 = fminf(bx2, sx2[j]);
                float yy2 = fminf(by2, sy2[j]);
                float iw = fmaxf(__fsub_rn(xx2, xx1), 0.f);
                float ih = fmaxf(__fsub_rn(yy2, yy1), 0.f);
                float inter = __fmul_rn(iw, ih);
                float denom = __fsub_rn(__fadd_rn(ba, sar[j]), inter);
                if (__fdiv_rn(inter, denom) > NMSTHR) srem[j] = 1;
            }
            if (count >= POSTK) break;
            __syncthreads();
        }
    }
    __syncthreads();

    for (int t = tid; t < POSTK; t += blockDim.x) {
        if (t < count) {
            int i = keepList[t];
            unsigned long long key = g_keys[i];
            out[t * 5 + 0] = sx1[i];
            out[t * 5 + 1] = sy1[i];
            out[t * 5 + 2] = sx2[i];
            out[t * 5 + 3] = sy2[i];
            out[t * 5 + 4] = __uint_as_float((unsigned)(key >> 32));
        } else {
            out[t * 5 + 0] = 0.f; out[t * 5 + 1] = 0.f; out[t * 5 + 2] = 0.f;
            out[t * 5 + 3] = 0.f; out[t * 5 + 4] = 0.f;
        }
    }
}

// ---------------- launch ----------------
extern "C" void kernel_launch(void* const* d_in, const int* in_sizes, int n_in,
                              void* d_out, int out_size)
{
    (void)in_sizes; (void)n_in; (void)out_size;
    const float* feat   = (const float*)d_in[1];
    const float* conv_w = (const float*)d_in[2];
    const float* conv_b = (const float*)d_in[3];
    const float* cls_w  = (const float*)d_in[4];
    const float* cls_b  = (const float*)d_in[5];
    const float* bbox_w = (const float*)d_in[6];
    const float* bbox_b = (const float*)d_in[7];
    float* out = (float*)d_out;

    conv3x3_relu<<<dim3(HW / 64, CH / 128), 256>>>(feat, conv_w, conv_b);
    heads_decode<<<GW, 128>>>(cls_w, cls_b, bbox_w, bbox_b);
    pad_keys<<<(NSORT - NANCH + 255) / 256, 256>>>();

    bitonic_local<<<NSORT / 2048, 1024>>>();
    for (int k = 4096; k <= NSORT; k <<= 1) {
        for (int j = k >> 1; j >= 2048; j >>= 1)
            bitonic_global<<<NSORT / 2 / 256, 256>>>(k, j);
        bitonic_finish<<<NSORT / 2048, 1024>>>(k);
    }

    const int nms_smem = TOPK * 5 * (int)sizeof(float) + TOPK + 64;
    cudaFuncSetAttribute(nms_out, cudaFuncAttributeMaxDynamicSharedMemorySize, nms_smem);
    nms_out<<<1, 1024, nms_smem>>>(out);
}

// round 3
// speedup vs baseline: 1.4036x; 1.4036x over previous
#include <cuda_runtime.h>
#include <cstdint>
#include <math.h>

// ---------------- problem constants ----------------
#define HW      16384           // 128*128 spatial
#define CH      256
#define KTOT    2304            // 256*9
#define NANCH   147456          // HW*9
#define TOPK    6000
#define POSTK   300
#define STRIDE  8.0f
#define IMSZ    1024.0f
#define DWCLIP  4.135166556742356f
#define NMSTHR  0.7f
#define MINSZ   16.0f

#define PLW     132
#define PLH     130
#define PLANE   (PLW*PLH)       // 17160
#define NPAD    (CH*PLANE)      // 4392960

#define NSEL    8192

// ---------------- scratch (device globals; no allocations allowed) ----------------
__device__ float g_rpnfeat[CH * HW];                 // 16.8 MB conv output
__device__ float g_featpad[NPAD];                    // 17.6 MB padded input
__device__ float g_wt[KTOT * CH];                    // 2.36 MB transposed weights [k][oc]
__device__ float g_boxes[NANCH * 4];                 // decoded boxes
__device__ unsigned long long g_keys[NANCH];         // (scorebits<<32)|~idx
__device__ unsigned long long g_sel[NSEL];           // selected candidates
__device__ int g_hist1[4096];
__device__ int g_hist2[4096];
__device__ int g_B1;
__device__ int g_cntgt;
__device__ unsigned g_T;
__device__ int g_selcnt;

// ---------------- f32x2 helpers ----------------
__device__ __forceinline__ unsigned long long dup2(float x) {
    unsigned long long r; unsigned u = __float_as_uint(x);
    asm("mov.b64 %0, {%1, %1};" : "=l"(r) : "r"(u));
    return r;
}
__device__ __forceinline__ void ffma2(unsigned long long& d, unsigned long long a, unsigned long long b) {
    asm("fma.rn.f32x2 %0, %1, %2, %0;" : "+l"(d) : "l"(a), "l"(b));
}

// =====================================================================
// prep: pad feature map into [256][130][132] with zero halo
// =====================================================================
__global__ __launch_bounds__(1024)
void prep_pad(const float* __restrict__ feat)
{
    int idx = blockIdx.x * 1024 + threadIdx.x;
    if (idx >= NPAD) return;
    int ic  = idx / PLANE;
    int rem = idx - ic * PLANE;
    int yy  = rem / PLW;
    int xx  = rem - yy * PLW;
    float v = 0.f;
    if (yy >= 1 && yy <= 128 && xx >= 1 && xx <= 128)
        v = feat[ic * HW + ((yy - 1) << 7) + (xx - 1)];
    g_featpad[idx] = v;
}

// prep: transpose weights w[oc][k] -> g_wt[k][oc]; zero histograms
__global__ __launch_bounds__(1024)
void prep_misc(const float* __restrict__ w)
{
    int idx = blockIdx.x * 1024 + threadIdx.x;   // 589824 = 576 blocks
    if (idx < 4096) g_hist1[idx] = 0;
    else if (idx < 8192) g_hist2[idx - 4096] = 0;
    int k = idx >> 8, oc = idx & 255;
    g_wt[idx] = w[oc * KTOT + k];
}

// =====================================================================
// conv 3x3 256->256 + bias + ReLU with packed FFMA2.
// Block: one image row y (BN=128 px) x 128 oc. 256 thr, 8Mx8N per thread.
// Accumulators packed as oc-pairs (32i+2ty, 32i+2ty+1).
// =====================================================================
__global__ __launch_bounds__(256, 2)
void conv3x3_relu(const float* __restrict__ bias)
{
    __shared__ float As[16][128];        // [kk][oc]
    __shared__ float Bs[16][144];        // [kk][skewed px]
    __shared__ int soff[KTOT];

    const int tid = threadIdx.x;
    const int tx = tid & 15;
    const int ty = tid >> 4;
    const int y = blockIdx.x;            // image row
    const int oc0 = blockIdx.y << 7;

    for (int k = tid; k < KTOT; k += 256) {
        int ic = k / 9, r = k - ic * 9, ky = r / 3, kx = r - ky * 3;
        soff[k] = ic * PLANE + ky * PLW + kx;
    }

    unsigned long long acc[4][8];
#pragma unroll
    for (int i = 0; i < 4; i++)
#pragma unroll
        for (int n = 0; n < 8; n++) acc[i][n] = 0ull;

    const int kkB = tid >> 4;                 // 0..15 (kk this thread loads for B)
    const int pxB = (tid & 15) * 8;
    const int bcolB = pxB + (((pxB >> 5) & 3) << 2);
    const int ybase = y * PLW;
    const int c0 = tx * 8 + (((tx >> 2) & 3) << 2);   // skewed compute col

    __syncthreads();

    for (int kb = 0; kb < KTOT; kb += 16) {
        // A tile: 16k x 128oc, coalesced from transposed weights
#pragma unroll
        for (int i = 0; i < 8; i++) {
            int idx = tid + (i << 8);
            As[idx >> 7][idx & 127] = g_wt[(kb + (idx >> 7)) * CH + oc0 + (idx & 127)];
        }
        // B tile: implicit im2col from padded feat, no bounds checks
        {
            const float* gp = g_featpad + soff[kb + kkB] + ybase + pxB;
#pragma unroll
            for (int j = 0; j < 8; j++) Bs[kkB][bcolB + j] = gp[j];
        }
        __syncthreads();

#pragma unroll
        for (int kk = 0; kk < 16; kk++) {
            const unsigned long long* A64 = (const unsigned long long*)&As[kk][0];
            unsigned long long a0 = A64[ty];
            unsigned long long a1 = A64[16 + ty];
            unsigned long long a2 = A64[32 + ty];
            unsigned long long a3 = A64[48 + ty];
            float4 bA = *(const float4*)&Bs[kk][c0];
            float4 bB = *(const float4*)&Bs[kk][c0 + 4];
            unsigned long long bd[8];
            bd[0] = dup2(bA.x); bd[1] = dup2(bA.y); bd[2] = dup2(bA.z); bd[3] = dup2(bA.w);
            bd[4] = dup2(bB.x); bd[5] = dup2(bB.y); bd[6] = dup2(bB.z); bd[7] = dup2(bB.w);
#pragma unroll
            for (int n = 0; n < 8; n++) {
                ffma2(acc[0][n], a0, bd[n]);
                ffma2(acc[1][n], a1, bd[n]);
                ffma2(acc[2][n], a2, bd[n]);
                ffma2(acc[3][n], a3, bd[n]);
            }
        }
        __syncthreads();
    }

#pragma unroll
    for (int i = 0; i < 4; i++) {
        int oc = oc0 + 32 * i + 2 * ty;
        float b0 = bias[oc], b1 = bias[oc + 1];
        float lo[8], hi[8];
#pragma unroll
        for (int n = 0; n < 8; n++) {
            lo[n] = fmaxf(__uint_as_float((unsigned)(acc[i][n] & 0xFFFFFFFFull)) + b0, 0.f);
            hi[n] = fmaxf(__uint_as_float((unsigned)(acc[i][n] >> 32)) + b1, 0.f);
        }
        int p0 = oc * HW + (y << 7) + tx * 8;
        *(float4*)&g_rpnfeat[p0]          = make_float4(lo[0], lo[1], lo[2], lo[3]);
        *(float4*)&g_rpnfeat[p0 + 4]      = make_float4(lo[4], lo[5], lo[6], lo[7]);
        *(float4*)&g_rpnfeat[p0 + HW]     = make_float4(hi[0], hi[1], hi[2], hi[3]);
        *(float4*)&g_rpnfeat[p0 + HW + 4] = make_float4(hi[4], hi[5], hi[6], hi[7]);
    }
}

// =====================================================================
// 1x1 heads + anchor decode + sigmoid + key pack (unchanged math from R1)
// =====================================================================
__global__ __launch_bounds__(128)
void heads_decode(const float* __restrict__ cls_w, const float* __restrict__ cls_b,
                  const float* __restrict__ bbox_w, const float* __restrict__ bbox_b)
{
    __shared__ float ws[45][256];
    const int tid = threadIdx.x;
    for (int i = tid; i < 9 * 256; i += 128)  ws[i >> 8][i & 255] = cls_w[i];
    for (int i = tid; i < 36 * 256; i += 128) ws[9 + (i >> 8)][i & 255] = bbox_w[i];
    __syncthreads();

    const int y = blockIdx.x;
    const int x = tid;
    const int p = (y << 7) + x;

    float acc[45];
#pragma unroll
    for (int j = 0; j < 45; j++) acc[j] = 0.f;

    for (int c = 0; c < 256; c++) {
        float v = g_rpnfeat[c * HW + p];
#pragma unroll
        for (int j = 0; j < 45; j++) acc[j] = fmaf(ws[j][c], v, acc[j]);
    }

    const float AR[3]  = {0.5f, 1.0f, 2.0f};
    const float SCL[3] = {128.f, 256.f, 512.f};
    const float sx = (float)x * STRIDE;
    const float sy = (float)y * STRIDE;

#pragma unroll
    for (int a = 0; a < 9; a++) {
        int ia = a / 3, is_ = a - ia * 3;
        float hr  = sqrtf(AR[ia]);
        float wr  = __fdiv_rn(1.0f, hr);
        float hsv = __fmul_rn(hr, SCL[is_]);
        float wsv = __fmul_rn(wr, SCL[is_]);
        float bx1 = rintf(__fmul_rn(-wsv, 0.5f));
        float by1 = rintf(__fmul_rn(-hsv, 0.5f));
        float bx2 = rintf(__fmul_rn(wsv, 0.5f));
        float by2 = rintf(__fmul_rn(hsv, 0.5f));
        float ax1 = __fadd_rn(sx, bx1), ay1 = __fadd_rn(sy, by1);
        float ax2 = __fadd_rn(sx, bx2), ay2 = __fadd_rn(sy, by2);
        float aw = __fsub_rn(ax2, ax1), ah = __fsub_rn(ay2, ay1);
        float cx = __fadd_rn(ax1, __fmul_rn(0.5f, aw));
        float cy = __fadd_rn(ay1, __fmul_rn(0.5f, ah));

        float dx = acc[9 + a * 4 + 0] + bbox_b[a * 4 + 0];
        float dy = acc[9 + a * 4 + 1] + bbox_b[a * 4 + 1];
        float dw = fminf(acc[9 + a * 4 + 2] + bbox_b[a * 4 + 2], DWCLIP);
        float dh = fminf(acc[9 + a * 4 + 3] + bbox_b[a * 4 + 3], DWCLIP);

        float px = __fadd_rn(__fmul_rn(dx, aw), cx);
        float py = __fadd_rn(__fmul_rn(dy, ah), cy);
        float pw = __fmul_rn((float)exp((double)dw), aw);
        float ph = __fmul_rn((float)exp((double)dh), ah);

        float x1 = __fsub_rn(px, __fmul_rn(0.5f, pw));
        float y1 = __fsub_rn(py, __fmul_rn(0.5f, ph));
        float x2 = __fadd_rn(px, __fmul_rn(0.5f, pw));
        float y2 = __fadd_rn(py, __fmul_rn(0.5f, ph));

        int idx = p * 9 + a;
        g_boxes[idx * 4 + 0] = x1;
        g_boxes[idx * 4 + 1] = y1;
        g_boxes[idx * 4 + 2] = x2;
        g_boxes[idx * 4 + 3] = y2;

        float cls = acc[a] + cls_b[a];
        float s = (float)(1.0 / (1.0 + exp(-(double)cls)));
        unsigned sb = __float_as_uint(s);
        g_keys[idx] = ((unsigned long long)sb << 32) | (unsigned)(0xFFFFFFFFu - (unsigned)idx);
    }
}

// =====================================================================
// Two-level radix select: exact top-24-bit threshold for the 6000th key.
// =====================================================================
__global__ __launch_bounds__(1024)
void hist_top()
{
    __shared__ int h[4096];
    const int tid = threadIdx.x;
    for (int i = tid; i < 4096; i += 1024) h[i] = 0;
    __syncthreads();
    for (int i = blockIdx.x * 1024 + tid; i < NANCH; i += gridDim.x * 1024)
        atomicAdd(&h[(unsigned)(g_keys[i] >> 52)], 1);
    __syncthreads();
    for (int i = tid; i < 4096; i += 1024) {
        int v = h[i];
        if (v) atomicAdd(&g_hist1[i], v);
    }
}

__global__ __launch_bounds__(1024)
void hist_in_bin()
{
    __shared__ int h[4096];
    const int tid = threadIdx.x;
    const unsigned b1 = (unsigned)g_B1;
    for (int i = tid; i < 4096; i += 1024) h[i] = 0;
    __syncthreads();
    for (int i = blockIdx.x * 1024 + tid; i < NANCH; i += gridDim.x * 1024) {
        unsigned long long key = g_keys[i];
        if ((unsigned)(key >> 52) == b1)
            atomicAdd(&h[(unsigned)((key >> 40) & 0xFFFull)], 1);
    }
    __syncthreads();
    for (int i = tid; i < 4096; i += 1024) {
        int v = h[i];
        if (v) atomicAdd(&g_hist2[i], v);
    }
}

__global__ __launch_bounds__(1024)
void scan_select(int phase)
{
    __shared__ int s[1024];
    const int t = threadIdx.x;
    const int* h = phase ? g_hist2 : g_hist1;
    const int base = phase ? g_cntgt : 0;
    int c[4];
    c[0] = h[4 * t]; c[1] = h[4 * t + 1]; c[2] = h[4 * t + 2]; c[3] = h[4 * t + 3];
    int v = c[0] + c[1] + c[2] + c[3];
    s[t] = v;
    __syncthreads();
    for (int off = 1; off < 1024; off <<= 1) {
        int add = (t + off < 1024) ? s[t + off] : 0;
        __syncthreads();
        v += add;
        s[t] = v;
        __syncthreads();
    }
    int suff = s[t];
    int above = (t < 1023) ? s[t + 1] : 0;
    if (base + above < TOPK && base + suff >= TOPK) {
        int cum = base + above;
#pragma unroll
        for (int b = 3; b >= 0; b--) {
            int hb = c[b];
            if (cum + hb >= TOPK) {
                if (phase == 0) { g_B1 = 4 * t + b; g_cntgt = cum; }
                else            { g_T = ((unsigned)g_B1 << 12) | (unsigned)(4 * t + b); }
                break;
            }
            cum += hb;
        }
    }
    if (phase) {
        if (t == 0) g_selcnt = 0;
        for (int i = t; i < NSEL; i += 1024) g_sel[i] = 0ull;
    }
}

__global__ __launch_bounds__(1024)
void compact_sel()
{
    const unsigned T = g_T;
    for (int i = blockIdx.x * 1024 + threadIdx.x; i < NANCH; i += gridDim.x * 1024) {
        unsigned long long key = g_keys[i];
        if ((unsigned)(key >> 40) >= T) {
            int p = atomicAdd(&g_selcnt, 1);
            if (p < NSEL) g_sel[p] = key;
        }
    }
}

// =====================================================================
// Sort the <=8192 candidates descending: 4x local bitonic + 1-block merge.
// =====================================================================
__global__ __launch_bounds__(1024)
void sel_local()
{
    __shared__ unsigned long long s[2048];
    const int base = blockIdx.x << 11;
    s[threadIdx.x]        = g_sel[base + threadIdx.x];
    s[threadIdx.x + 1024] = g_sel[base + threadIdx.x + 1024];
    __syncthreads();
    for (int k = 2; k <= 2048; k <<= 1) {
        for (int j = k >> 1; j > 0; j >>= 1) {
            int t = threadIdx.x;
            int i = (t << 1) - (t & (j - 1));
            bool desc = (((base + i) & k) == 0);
            unsigned long long a = s[i], b = s[i + j];
            if ((a < b) == desc) { s[i] = b; s[i + j] = a; }
            __syncthreads();
        }
    }
    g_sel[base + threadIdx.x]        = s[threadIdx.x];
    g_sel[base + threadIdx.x + 1024] = s[threadIdx.x + 1024];
}

__global__ __launch_bounds__(1024)
void sel_merge()
{
    extern __shared__ unsigned long long s[];
    const int tid = threadIdx.x;
#pragma unroll
    for (int q = 0; q < 8; q++) s[tid + (q << 10)] = g_sel[tid + (q << 10)];
    __syncthreads();
    for (int k = 4096; k <= NSEL; k <<= 1) {
        for (int j = k >> 1; j > 0; j >>= 1) {
#pragma unroll
            for (int q = 0; q < 4; q++) {
                int t = tid + (q << 10);
                int i = (t << 1) - (t & (j - 1));
                bool desc = ((i & k) == 0);
                unsigned long long a = s[i], b = s[i + j];
                if ((a < b) == desc) { s[i] = b; s[i + j] = a; }
            }
            __syncthreads();
        }
    }
#pragma unroll
    for (int q = 0; q < 8; q++) g_sel[tid + (q << 10)] = s[tid + (q << 10)];
}

// =====================================================================
// clip + min-size + greedy NMS (early exit at 300) + output 300x5
// =====================================================================
__global__ __launch_bounds__(1024)
void nms_out(float* __restrict__ out)
{
    extern __shared__ float sm[];
    float* sx1 = sm;
    float* sy1 = sm + TOPK;
    float* sx2 = sm + 2 * TOPK;
    float* sy2 = sm + 3 * TOPK;
    float* sar = sm + 4 * TOPK;
    unsigned char* srem = (unsigned char*)(sm + 5 * TOPK);
    __shared__ int keepList[POSTK];

    const int tid = threadIdx.x;
    for (int i = tid; i < TOPK; i += blockDim.x) {
        unsigned long long key = g_sel[i];
        unsigned idx = 0xFFFFFFFFu - (unsigned)(key & 0xFFFFFFFFull);
        float b0 = g_boxes[idx * 4 + 0];
        float b1 = g_boxes[idx * 4 + 1];
        float b2 = g_boxes[idx * 4 + 2];
        float b3 = g_boxes[idx * 4 + 3];
        float x1 = fminf(fmaxf(b0, 0.f), IMSZ);
        float y1 = fminf(fmaxf(b1, 0.f), IMSZ);
        float x2 = fminf(fmaxf(b2, 0.f), IMSZ);
        float y2 = fminf(fmaxf(b3, 0.f), IMSZ);
        float wv = __fsub_rn(x2, x1);
        float hv = __fsub_rn(y2, y1);
        sx1[i] = x1; sy1[i] = y1; sx2[i] = x2; sy2[i] = y2;
        sar[i] = __fmul_rn(wv, hv);
        srem[i] = (wv >= MINSZ && hv >= MINSZ) ? 0 : 1;
    }
    __syncthreads();

    int count = 0;
    for (int i = 0; i < TOPK; i++) {
        if (srem[i] == 0) {
            if (tid == 0) keepList[count] = i;
            count++;
            float bx1 = sx1[i], by1 = sy1[i], bx2 = sx2[i], by2 = sy2[i], ba = sar[i];
            for (int j = i + 1 + tid; j < TOPK; j += blockDim.x) {
                if (srem[j]) continue;
                float xx1 = fmaxf(bx1, sx1[j]);
                float yy1 = fmaxf(by1, sy1[j]);
                float xx2 = fminf(bx2, sx2[j]);
                float yy2 = fminf(by2, sy2[j]);
                float iw = fmaxf(__fsub_rn(xx2, xx1), 0.f);
                float ih = fmaxf(__fsub_rn(yy2, yy1), 0.f);
                float inter = __fmul_rn(iw, ih);
                float denom = __fsub_rn(__fadd_rn(ba, sar[j]), inter);
                if (__fdiv_rn(inter, denom) > NMSTHR) srem[j] = 1;
            }
            if (count >= POSTK) break;
            __syncthreads();
        }
    }
    __syncthreads();

    for (int t = tid; t < POSTK; t += blockDim.x) {
        if (t < count) {
            int i = keepList[t];
            unsigned long long key = g_sel[i];
            out[t * 5 + 0] = sx1[i];
            out[t * 5 + 1] = sy1[i];
            out[t * 5 + 2] = sx2[i];
            out[t * 5 + 3] = sy2[i];
            out[t * 5 + 4] = __uint_as_float((unsigned)(key >> 32));
        } else {
            out[t * 5 + 0] = 0.f; out[t * 5 + 1] = 0.f; out[t * 5 + 2] = 0.f;
            out[t * 5 + 3] = 0.f; out[t * 5 + 4] = 0.f;
        }
    }
}

// ---------------- launch ----------------
extern "C" void kernel_launch(void* const* d_in, const int* in_sizes, int n_in,
                              void* d_out, int out_size)
{
    (void)in_sizes; (void)n_in; (void)out_size;
    const float* feat   = (const float*)d_in[1];
    const float* conv_w = (const float*)d_in[2];
    const float* conv_b = (const float*)d_in[3];
    const float* cls_w  = (const float*)d_in[4];
    const float* cls_b  = (const float*)d_in[5];
    const float* bbox_w = (const float*)d_in[6];
    const float* bbox_b = (const float*)d_in[7];
    float* out = (float*)d_out;

    prep_pad<<<(NPAD + 1023) / 1024, 1024>>>(feat);
    prep_misc<<<(KTOT * CH) / 1024, 1024>>>(conv_w);
    conv3x3_relu<<<dim3(128, 2), 256>>>(conv_b);
    heads_decode<<<128, 128>>>(cls_w, cls_b, bbox_w, bbox_b);
    hist_top<<<144, 1024>>>();
    scan_select<<<1, 1024>>>(0);
    hist_in_bin<<<144, 1024>>>();
    scan_select<<<1, 1024>>>(1);
    compact_sel<<<144, 1024>>>();
    sel_local<<<4, 1024>>>();
    cudaFuncSetAttribute(sel_merge, cudaFuncAttributeMaxDynamicSharedMemorySize, NSEL * 8);
    sel_merge<<<1, 1024, NSEL * 8>>>();
    const int nms_smem = TOPK * 5 * (int)sizeof(float) + TOPK + 64;
    cudaFuncSetAttribute(nms_out, cudaFuncAttributeMaxDynamicSharedMemorySize, nms_smem);
    nms_out<<<1, 1024, nms_smem>>>(out);
}